// round 14
// baseline (speedup 1.0000x reference)
#include <cuda_runtime.h>
#include <cstdint>

#define T_NODES 80000          // B*N = 16*5000
#define C_DIM   128
#define HF_DIM  128            // H*F = 2*64
#define E_EDGES 1280000
#define SLOT_CAP 64            // max in-degree capacity (Poisson(16); max ~42)
#define LOG2E 1.4426950408889634f

// ---------------- static device scratch (zero-initialized at load) ----------------
__device__ __align__(16) float g_xl[T_NODES * HF_DIM];   // 40.96 MB
__device__ __align__(16) float g_xr[T_NODES * HF_DIM];   // 40.96 MB
__device__ int g_deg[T_NODES];            // invariant: zero at kernel_launch entry
__device__ int g_slot[T_NODES * SLOT_CAP + 8];  // src byte offsets (src<<9); 20.5 MB

// ---------------- tf32 helpers ----------------
__device__ __forceinline__ uint32_t f2tf32(float v) {
    uint32_t r;
    asm("cvt.rna.tf32.f32 %0, %1;" : "=r"(r) : "f"(v));
    return r;
}
__device__ __forceinline__ void mma_tf32(float* d, const uint32_t* a, const uint32_t* b) {
    asm("mma.sync.aligned.m16n8k8.row.col.f32.tf32.tf32.f32 "
        "{%0,%1,%2,%3}, {%4,%5,%6,%7}, {%8,%9}, {%0,%1,%2,%3};"
        : "+f"(d[0]), "+f"(d[1]), "+f"(d[2]), "+f"(d[3])
        : "r"(a[0]), "r"(a[1]), "r"(a[2]), "r"(a[3]),
          "r"(b[0]), "r"(b[1]));
}

// ---------------- K1: fused tf32 GEMM pair + placement, reg-pipelined staging ---
// 512 threads / 16 warps, 1 CTA/SM. Chunk c+1's global loads are issued before
// chunk c's MMA loop, hiding LDG latency under tensor work.
__global__ void __launch_bounds__(512, 1)
gemm_kernel(const float* __restrict__ X,
            const float* __restrict__ Wl, const float* __restrict__ bl,
            const float* __restrict__ Wr, const float* __restrict__ br,
            const int* __restrict__ ei, int E) {
    __shared__ uint32_t A_s[4096];       // [k8(4)][ma(8)][lane(32)][rg(4)] XOR-skewed
    __shared__ uint32_t B_s[2][4096];    // per group: [k8(4)][na(16)][lane(32)][rg(2)]

    const int t = threadIdx.x;

    // edge placement: pos = atomicAdd(deg[dst]); slot[dst*CAP+pos] = src<<9
    {
        const int nthr = gridDim.x * 512;
        int gid = blockIdx.x * 512 + t;
        if ((E & 3) == 0) {
            const int4* __restrict__ s4 = (const int4*)ei;
            const int4* __restrict__ d4 = (const int4*)(ei + E);
            for (int e = gid; e < (E >> 2); e += nthr) {
                int4 s = s4[e];
                int4 dd = d4[e];
                int p0 = atomicAdd(&g_deg[dd.x], 1);
                int p1 = atomicAdd(&g_deg[dd.y], 1);
                int p2 = atomicAdd(&g_deg[dd.z], 1);
                int p3 = atomicAdd(&g_deg[dd.w], 1);
                g_slot[dd.x * SLOT_CAP + p0] = s.x << 9;
                g_slot[dd.y * SLOT_CAP + p1] = s.y << 9;
                g_slot[dd.z * SLOT_CAP + p2] = s.z << 9;
                g_slot[dd.w * SLOT_CAP + p3] = s.w << 9;
            }
        } else {
            for (int e = gid; e < E; e += nthr) {
                int dst = ei[E + e];
                int pos = atomicAdd(&g_deg[dst], 1);
                g_slot[dst * SLOT_CAP + pos] = ei[e] << 9;
            }
        }
    }

    const int lane = t & 31;
    const int wid  = t >> 5;          // 0..15
    const int g    = wid >> 3;        // warp group: 0 = xl, 1 = xr
    const int w8   = wid & 7;
    const int wm   = w8 & 3;
    const int wn   = w8 >> 2;
    const int rowBase = blockIdx.x * 128;

    const int tig = lane & 3;
    const int grp = lane >> 2;

    const float* __restrict__ bvec  = g ? br : bl;
    float* __restrict__ Y           = g ? g_xr : g_xl;

    const int a_row = t >> 2;
    const int a_k8  = t & 3;
    const int a_r   = a_row & 15;
    const int a_ma  = a_row >> 4;
    const int a_atombase = (a_k8 * 8 + a_ma) * 128;
    const int a_skew = a_k8 * 4;
    const float* __restrict__ a_src = X + (size_t)(rowBase + a_row) * C_DIM + a_k8 * 8;

    // B staging geometry for this thread (fixed across chunks)
    const int b_bg = (t >> 8) & 1;                 // which W this thread stages
    const int b_na = (t >> 2) & 15;                // hmm see loop below
    // We stage with the q-loop (8 iters) to cover [bg(2)][na(16)][k8(4)] combos.

    float aReg[8];
    float bReg[16];

    // ---- preload chunk 0 ----
    {
        float4 v0 = *(const float4*)a_src;
        float4 v1 = *(const float4*)(a_src + 4);
        aReg[0]=v0.x; aReg[1]=v0.y; aReg[2]=v0.z; aReg[3]=v0.w;
        aReg[4]=v1.x; aReg[5]=v1.y; aReg[6]=v1.z; aReg[7]=v1.w;
#pragma unroll
        for (int q = 0; q < 8; q++) {
            int combo = q * 16 + wid;
            int bg  = combo >> 6;
            int rem = combo & 63;
            int na  = rem >> 2;
            int k8  = rem & 3;
            const float* __restrict__ WW = bg ? Wr : Wl;
            int k0 = k8 * 8 + tig;
            int n  = na * 8 + grp;
            bReg[q * 2]     = WW[k0 * HF_DIM + n];
            bReg[q * 2 + 1] = WW[(k0 + 4) * HF_DIM + n];
        }
    }

    float d[2][8][4];
#pragma unroll
    for (int ma = 0; ma < 2; ma++)
#pragma unroll
        for (int na = 0; na < 8; na++)
#pragma unroll
            for (int r = 0; r < 4; r++) d[ma][na][r] = 0.f;

#pragma unroll 1
    for (int chunk = 0; chunk < 4; chunk++) {
        // ---- commit staged registers to smem ----
#pragma unroll
        for (int j = 0; j < 8; j++) {
            int ln = (a_r & 7) * 4 + (j & 3);
            int rg = (a_r >> 3) + 2 * (j >> 2);
            A_s[a_atombase + ((ln * 4 + rg) ^ a_skew)] = f2tf32(aReg[j]);
        }
#pragma unroll
        for (int q = 0; q < 8; q++) {
            int combo = q * 16 + wid;
            int bg  = combo >> 6;
            int rem = combo & 63;
            int na  = rem >> 2;
            int k8  = rem & 3;
            uint2 val;
            val.x = f2tf32(bReg[q * 2]);
            val.y = f2tf32(bReg[q * 2 + 1]);
            *(uint2*)&B_s[bg][((k8 * 16 + na) * 32 + lane) * 2] = val;
        }
        __syncthreads();

        // ---- issue next chunk's global loads (overlap with MMA below) ----
        if (chunk < 3) {
            const int kc = (chunk + 1) * 32;
            float4 v0 = *(const float4*)(a_src + kc);
            float4 v1 = *(const float4*)(a_src + kc + 4);
            aReg[0]=v0.x; aReg[1]=v0.y; aReg[2]=v0.z; aReg[3]=v0.w;
            aReg[4]=v1.x; aReg[5]=v1.y; aReg[6]=v1.z; aReg[7]=v1.w;
#pragma unroll
            for (int q = 0; q < 8; q++) {
                int combo = q * 16 + wid;
                int bg  = combo >> 6;
                int rem = combo & 63;
                int na  = rem >> 2;
                int k8  = rem & 3;
                const float* __restrict__ WW = bg ? Wr : Wl;
                int k0 = kc + k8 * 8 + tig;
                int n  = na * 8 + grp;
                bReg[q * 2]     = WW[k0 * HF_DIM + n];
                bReg[q * 2 + 1] = WW[(k0 + 4) * HF_DIM + n];
            }
        }

        // ---- MMA over this chunk's smem ----
#pragma unroll
        for (int k8 = 0; k8 < 4; k8++) {
            const int skew = k8 * 4;
            uint32_t af[2][4];
#pragma unroll
            for (int ma = 0; ma < 2; ma++) {
                int base = (k8 * 8 + wm * 2 + ma) * 128 + ((lane * 4) ^ skew);
                uint4 h = *(const uint4*)&A_s[base];
                af[ma][0] = h.x; af[ma][1] = h.y; af[ma][2] = h.z; af[ma][3] = h.w;
            }
            uint32_t bf[8][2];
#pragma unroll
            for (int na = 0; na < 8; na++) {
                uint2 b2 = *(const uint2*)&B_s[g][((k8 * 16 + wn * 8 + na) * 32 + lane) * 2];
                bf[na][0] = b2.x; bf[na][1] = b2.y;
            }
#pragma unroll
            for (int ma = 0; ma < 2; ma++)
#pragma unroll
                for (int na = 0; na < 8; na++)
                    mma_tf32(d[ma][na], af[ma], bf[na]);
        }
        __syncthreads();
    }

    // epilogue: add bias, store
#pragma unroll
    for (int ma = 0; ma < 2; ma++) {
        int row0 = rowBase + wm * 32 + ma * 16 + grp;
        int row1 = row0 + 8;
#pragma unroll
        for (int na = 0; na < 8; na++) {
            int col = wn * 64 + na * 8 + tig * 2;
            float2 bb = *(const float2*)&bvec[col];
            float2 o0 = { d[ma][na][0] + bb.x, d[ma][na][1] + bb.y };
            float2 o1 = { d[ma][na][2] + bb.x, d[ma][na][3] + bb.y };
            *(float2*)&Y[(size_t)row0 * HF_DIM + col] = o0;
            *(float2*)&Y[(size_t)row1 * HF_DIM + col] = o1;
        }
    }
}

// ---------------- K2: softmax + aggregation (R12 champion body) ----------------
__device__ __forceinline__ float edge_logit(float4 xs, float4 xr,
                                            float4 av6, float4 av4) {
    float t0 = xs.x + xr.x, t1 = xs.y + xr.y, t2 = xs.z + xr.z, t3 = xs.w + xr.w;
    float p;
    p = t0 * av6.x;
    p = fmaf(fabsf(t0), av4.x, p);
    p = fmaf(t1, av6.y, p);
    p = fmaf(fabsf(t1), av4.y, p);
    p = fmaf(t2, av6.z, p);
    p = fmaf(fabsf(t2), av4.z, p);
    p = fmaf(t3, av6.w, p);
    p = fmaf(fabsf(t3), av4.w, p);
    p += __shfl_xor_sync(0xffffffffu, p, 1);
    p += __shfl_xor_sync(0xffffffffu, p, 2);
    p += __shfl_xor_sync(0xffffffffu, p, 4);
    p += __shfl_xor_sync(0xffffffffu, p, 8);
    return p;
}

// index for edge i from the warp's register-resident slot row (i uniform)
__device__ __forceinline__ int sel_idx(int i, int a, int b) {
    int r = (i < 32) ? a : b;
    return __shfl_sync(0xffffffffu, r, i & 31);
}

__global__ void __launch_bounds__(256, 4)
agg_kernel(const float* __restrict__ att, const float* __restrict__ bias,
           float* __restrict__ out) {
    int warp_id = (blockIdx.x * blockDim.x + threadIdx.x) >> 5;
    int lane = threadIdx.x & 31;
    if (warp_id >= T_NODES) return;
    const int d = warp_id;
    const int fbase = lane * 4;

    const char* __restrict__ xlb = (const char*)g_xl;
    const unsigned loff = (unsigned)lane << 4;   // lane * 16 bytes

    // one coalesced read covers the whole bucket row -> indices in registers
    const int n = g_deg[d];
    if (lane == 0) g_deg[d] = 0;              // self-clean for next launch
    const int* __restrict__ sp = g_slot + d * SLOT_CAP;
    int idxA = __ldg(&sp[lane]);                       // edges 0..31
    int idxB = (n > 28) ? __ldg(&sp[32 + lane]) : 0;   // edges 32..63 (prefetch margin)

    float4 a = *(const float4*)&att[fbase];
    float4 av6, av4;
    av6.x = a.x * (0.6f * LOG2E); av4.x = a.x * (0.4f * LOG2E);
    av6.y = a.y * (0.6f * LOG2E); av4.y = a.y * (0.4f * LOG2E);
    av6.z = a.z * (0.6f * LOG2E); av4.z = a.z * (0.4f * LOG2E);
    av6.w = a.w * (0.6f * LOG2E); av4.w = a.w * (0.4f * LOG2E);

    float4 xr  = *(const float4*)((const char*)g_xr + ((unsigned)d << 9) + loff);
    float4 xld = *(const float4*)(xlb + ((unsigned)d << 9) + loff);

    const float lself = edge_logit(xld, xr, av6, av4);   // log2-domain baseline
    float den = 1.0f;
    float4 acc = xld;

    if (n > 0) {
        // prefetch pipeline depth 2; indices are register shuffles
        int s2 = sel_idx(2, idxA, idxB);
        int s3 = sel_idx(3, idxA, idxB);
        float4 x0 = *(const float4*)(xlb + (unsigned)sel_idx(0, idxA, idxB) + loff);
        float4 x1 = *(const float4*)(xlb + (unsigned)sel_idx(1, idxA, idxB) + loff);

        const int n2 = n & ~1;
        for (int i = 0; i < n2; i += 2) {
            float4 x2 = *(const float4*)(xlb + (unsigned)s2 + loff);
            float4 x3 = *(const float4*)(xlb + (unsigned)s3 + loff);
            s2 = sel_idx(i + 4, idxA, idxB);
            s3 = sel_idx(i + 5, idxA, idxB);

            float l0 = edge_logit(x0, xr, av6, av4);
            float l1 = edge_logit(x1, xr, av6, av4);
            float w0 = exp2f(l0 - lself);
            float w1 = exp2f(l1 - lself);

            den += w0 + w1;
            acc.x = fmaf(w0, x0.x, fmaf(w1, x1.x, acc.x));
            acc.y = fmaf(w0, x0.y, fmaf(w1, x1.y, acc.y));
            acc.z = fmaf(w0, x0.z, fmaf(w1, x1.z, acc.z));
            acc.w = fmaf(w0, x0.w, fmaf(w1, x1.w, acc.w));

            x0 = x2; x1 = x3;
        }
        if (n & 1) {
            // after the loop, x0 holds edge n-1
            float l0 = edge_logit(x0, xr, av6, av4);
            float w0 = exp2f(l0 - lself);
            den += w0;
            acc.x = fmaf(w0, x0.x, acc.x);
            acc.y = fmaf(w0, x0.y, acc.y);
            acc.z = fmaf(w0, x0.z, acc.z);
            acc.w = fmaf(w0, x0.w, acc.w);
        }
    }

    float inv = 1.0f / den;
    float4 bv = *(const float4*)&bias[fbase];
    float4 r;
    r.x = fmaf(acc.x, inv, bv.x);
    r.y = fmaf(acc.y, inv, bv.y);
    r.z = fmaf(acc.z, inv, bv.z);
    r.w = fmaf(acc.w, inv, bv.w);
    *(float4*)((char*)out + ((unsigned)d << 9) + loff) = r;
}

// ---------------- launch (2 kernels) ----------------
extern "C" void kernel_launch(void* const* d_in, const int* in_sizes, int n_in,
                              void* d_out, int out_size) {
    const float* x    = (const float*)d_in[0];
    const int*   ei   = (const int*)d_in[1];
    const float* Wl   = (const float*)d_in[2];
    const float* bl   = (const float*)d_in[3];
    const float* Wr   = (const float*)d_in[4];
    const float* br   = (const float*)d_in[5];
    const float* att  = (const float*)d_in[6];
    const float* bias = (const float*)d_in[7];
    float* out = (float*)d_out;

    const int E = in_sizes[1] / 2;

    gemm_kernel<<<T_NODES / 128, 512>>>(x, Wl, bl, Wr, br, ei, E);
    agg_kernel<<<(T_NODES * 32 + 255) / 256, 256>>>(att, bias, out);
}

// round 15
// speedup vs baseline: 1.9236x; 1.9236x over previous
#include <cuda_runtime.h>
#include <cstdint>

#define T_NODES 80000          // B*N = 16*5000
#define C_DIM   128
#define HF_DIM  128            // H*F = 2*64
#define E_EDGES 1280000
#define SLOT_CAP 96            // max in-degree capacity (do NOT change: R14 regression)
#define LOG2E 1.4426950408889634f

// ---------------- static device scratch (zero-initialized at load) ----------------
__device__ __align__(16) float g_xl[T_NODES * HF_DIM];   // 40.96 MB
__device__ __align__(16) float g_xr[T_NODES * HF_DIM];   // 40.96 MB
__device__ int g_deg[T_NODES];            // invariant: zero at kernel_launch entry
__device__ int g_slot[T_NODES * SLOT_CAP + 8];  // src byte offsets (src<<9); 30.7 MB

// ---------------- tf32 helpers ----------------
__device__ __forceinline__ uint32_t f2tf32(float v) {
    uint32_t r;
    asm("cvt.rna.tf32.f32 %0, %1;" : "=r"(r) : "f"(v));
    return r;
}
__device__ __forceinline__ void mma_tf32(float* d, const uint32_t* a, const uint32_t* b) {
    asm("mma.sync.aligned.m16n8k8.row.col.f32.tf32.tf32.f32 "
        "{%0,%1,%2,%3}, {%4,%5,%6,%7}, {%8,%9}, {%0,%1,%2,%3};"
        : "+f"(d[0]), "+f"(d[1]), "+f"(d[2]), "+f"(d[3])
        : "r"(a[0]), "r"(a[1]), "r"(a[2]), "r"(a[3]),
          "r"(b[0]), "r"(b[1]));
}

// ---------------- K1: fused tf32 GEMM pair + interleaved edge placement --------
// 512 threads / 16 warps. Placement spread across the 4 chunk iterations:
// each chunk, 1/4 of threads place their edges after their MMA block, filling
// the straggler window before __syncthreads instead of a prologue atomic burst.
__global__ void __launch_bounds__(512, 1)
gemm_kernel(const float* __restrict__ X,
            const float* __restrict__ Wl, const float* __restrict__ bl,
            const float* __restrict__ Wr, const float* __restrict__ br,
            const int* __restrict__ ei, int E) {
    __shared__ uint32_t A_s[4096];       // [k8(4)][ma(8)][lane(32)][rg(4)] XOR-skewed
    __shared__ uint32_t B_s[2][4096];    // per group: [k8(4)][na(16)][lane(32)][rg(2)]

    const int t = threadIdx.x;
    const int nthr = gridDim.x * 512;
    const int gid = blockIdx.x * 512 + t;

    // fallback scalar placement for non-multiple-of-4 E (not hit for this dataset)
    if ((E & 3) != 0) {
        for (int e = gid; e < E; e += nthr) {
            int dst = ei[E + e];
            int pos = atomicAdd(&g_deg[dst], 1);
            g_slot[dst * SLOT_CAP + pos] = ei[e] << 9;
        }
        E &= ~3;   // vector part handled below
    }

    const int lane = t & 31;
    const int wid  = t >> 5;          // 0..15
    const int g    = wid >> 3;        // warp group: 0 = xl, 1 = xr
    const int w8   = wid & 7;
    const int wm   = w8 & 3;
    const int wn   = w8 >> 2;
    const int rowBase = blockIdx.x * 128;

    const int tig = lane & 3;
    const int grp = lane >> 2;

    const float* __restrict__ bvec  = g ? br : bl;
    float* __restrict__ Y           = g ? g_xr : g_xl;

    const int a_row = t >> 2;
    const int a_k8  = t & 3;
    const int a_r   = a_row & 15;
    const int a_ma  = a_row >> 4;
    const int a_atombase = (a_k8 * 8 + a_ma) * 128;
    const int a_skew = a_k8 * 4;

    float d[2][8][4];
#pragma unroll
    for (int ma = 0; ma < 2; ma++)
#pragma unroll
        for (int na = 0; na < 8; na++)
#pragma unroll
            for (int r = 0; r < 4; r++) d[ma][na][r] = 0.f;

#pragma unroll 1
    for (int chunk = 0; chunk < 4; chunk++) {
        const int kc = chunk * 32;

        // stage A chunk (128 rows x 32 k): coalesced LDG.128, skewed STS
        {
            const float* xp = X + (size_t)(rowBase + a_row) * C_DIM + kc + a_k8 * 8;
            float4 v0 = *(const float4*)xp;
            float4 v1 = *(const float4*)(xp + 4);
            float vv[8] = { v0.x, v0.y, v0.z, v0.w, v1.x, v1.y, v1.z, v1.w };
#pragma unroll
            for (int j = 0; j < 8; j++) {
                int ln = (a_r & 7) * 4 + (j & 3);
                int rg = (a_r >> 3) + 2 * (j >> 2);
                A_s[a_atombase + ((ln * 4 + rg) ^ a_skew)] = f2tf32(vv[j]);
            }
        }
        // stage both B chunks (32 k x 128 n each), fragment-ordered
#pragma unroll
        for (int q = 0; q < 8; q++) {
            int combo = q * 16 + wid;
            int bg  = combo >> 6;
            int rem = combo & 63;
            int na  = rem >> 2;
            int k8  = rem & 3;
            const float* __restrict__ WW = bg ? Wr : Wl;
            int k0 = kc + k8 * 8 + tig;
            int n  = na * 8 + grp;
            uint2 val;
            val.x = f2tf32(WW[k0 * HF_DIM + n]);
            val.y = f2tf32(WW[(k0 + 4) * HF_DIM + n]);
            *(uint2*)&B_s[bg][((k8 * 16 + na) * 32 + lane) * 2] = val;
        }
        __syncthreads();

        // MMA over this chunk's smem
#pragma unroll
        for (int k8 = 0; k8 < 4; k8++) {
            const int skew = k8 * 4;
            uint32_t af[2][4];
#pragma unroll
            for (int ma = 0; ma < 2; ma++) {
                int base = (k8 * 8 + wm * 2 + ma) * 128 + ((lane * 4) ^ skew);
                uint4 h = *(const uint4*)&A_s[base];
                af[ma][0] = h.x; af[ma][1] = h.y; af[ma][2] = h.z; af[ma][3] = h.w;
            }
            uint32_t bf[8][2];
#pragma unroll
            for (int na = 0; na < 8; na++) {
                uint2 b2 = *(const uint2*)&B_s[g][((k8 * 16 + wn * 8 + na) * 32 + lane) * 2];
                bf[na][0] = b2.x; bf[na][1] = b2.y;
            }
#pragma unroll
            for (int ma = 0; ma < 2; ma++)
#pragma unroll
                for (int na = 0; na < 8; na++)
                    mma_tf32(d[ma][na], af[ma], bf[na]);
        }

        // interleaved edge placement: 1/4 of threads per chunk, after their MMA.
        // Atomic/store latency overlaps the straggler wait at __syncthreads.
        if (((gid ^ chunk) & 3) == 0) {
            const int4* __restrict__ s4 = (const int4*)ei;
            const int4* __restrict__ d4 = (const int4*)(ei + E);
            for (int e = gid; e < (E >> 2); e += nthr) {
                int4 s = s4[e];
                int4 dd = d4[e];
                int p0 = atomicAdd(&g_deg[dd.x], 1);
                int p1 = atomicAdd(&g_deg[dd.y], 1);
                int p2 = atomicAdd(&g_deg[dd.z], 1);
                int p3 = atomicAdd(&g_deg[dd.w], 1);
                g_slot[dd.x * SLOT_CAP + p0] = s.x << 9;
                g_slot[dd.y * SLOT_CAP + p1] = s.y << 9;
                g_slot[dd.z * SLOT_CAP + p2] = s.z << 9;
                g_slot[dd.w * SLOT_CAP + p3] = s.w << 9;
            }
        }
        __syncthreads();
    }

    // epilogue: add bias, store
#pragma unroll
    for (int ma = 0; ma < 2; ma++) {
        int row0 = rowBase + wm * 32 + ma * 16 + grp;
        int row1 = row0 + 8;
#pragma unroll
        for (int na = 0; na < 8; na++) {
            int col = wn * 64 + na * 8 + tig * 2;
            float2 bb = *(const float2*)&bvec[col];
            float2 o0 = { d[ma][na][0] + bb.x, d[ma][na][1] + bb.y };
            float2 o1 = { d[ma][na][2] + bb.x, d[ma][na][3] + bb.y };
            *(float2*)&Y[(size_t)row0 * HF_DIM + col] = o0;
            *(float2*)&Y[(size_t)row1 * HF_DIM + col] = o1;
        }
    }
}

// ---------------- K2: softmax + aggregation (R12 champion body, untouched) -----
__device__ __forceinline__ float edge_logit(float4 xs, float4 xr,
                                            float4 av6, float4 av4) {
    float t0 = xs.x + xr.x, t1 = xs.y + xr.y, t2 = xs.z + xr.z, t3 = xs.w + xr.w;
    float p;
    p = t0 * av6.x;
    p = fmaf(fabsf(t0), av4.x, p);
    p = fmaf(t1, av6.y, p);
    p = fmaf(fabsf(t1), av4.y, p);
    p = fmaf(t2, av6.z, p);
    p = fmaf(fabsf(t2), av4.z, p);
    p = fmaf(t3, av6.w, p);
    p = fmaf(fabsf(t3), av4.w, p);
    p += __shfl_xor_sync(0xffffffffu, p, 1);
    p += __shfl_xor_sync(0xffffffffu, p, 2);
    p += __shfl_xor_sync(0xffffffffu, p, 4);
    p += __shfl_xor_sync(0xffffffffu, p, 8);
    return p;
}

// index for edge i from the warp's register-resident slot row (i uniform)
__device__ __forceinline__ int sel_idx(int i, int a, int b, int c) {
    int r = (i < 32) ? a : ((i < 64) ? b : c);
    return __shfl_sync(0xffffffffu, r, i & 31);
}

__global__ void __launch_bounds__(256, 4)
agg_kernel(const float* __restrict__ att, const float* __restrict__ bias,
           float* __restrict__ out) {
    int warp_id = (blockIdx.x * blockDim.x + threadIdx.x) >> 5;
    int lane = threadIdx.x & 31;
    if (warp_id >= T_NODES) return;
    const int d = warp_id;
    const int fbase = lane * 4;

    const char* __restrict__ xlb = (const char*)g_xl;
    const unsigned loff = (unsigned)lane << 4;   // lane * 16 bytes

    // one coalesced read covers the whole bucket row -> indices live in registers
    const int n = g_deg[d];
    if (lane == 0) g_deg[d] = 0;              // self-clean for next launch
    const int* __restrict__ sp = g_slot + d * SLOT_CAP;
    int idxA = __ldg(&sp[lane]);                       // edges 0..31
    int idxB = (n > 28) ? __ldg(&sp[32 + lane]) : 0;   // edges 32..63 (prefetch margin)
    int idxC = (n > 60) ? __ldg(&sp[64 + lane]) : 0;   // edges 64..95

    float4 a = *(const float4*)&att[fbase];
    float4 av6, av4;
    av6.x = a.x * (0.6f * LOG2E); av4.x = a.x * (0.4f * LOG2E);
    av6.y = a.y * (0.6f * LOG2E); av4.y = a.y * (0.4f * LOG2E);
    av6.z = a.z * (0.6f * LOG2E); av4.z = a.z * (0.4f * LOG2E);
    av6.w = a.w * (0.6f * LOG2E); av4.w = a.w * (0.4f * LOG2E);

    float4 xr  = *(const float4*)((const char*)g_xr + ((unsigned)d << 9) + loff);
    float4 xld = *(const float4*)(xlb + ((unsigned)d << 9) + loff);

    const float lself = edge_logit(xld, xr, av6, av4);   // log2-domain baseline
    float den = 1.0f;
    float4 acc = xld;

    if (n > 0) {
        // prefetch pipeline depth 2; indices are register shuffles (no mem latency)
        int s2 = sel_idx(2, idxA, idxB, idxC);
        int s3 = sel_idx(3, idxA, idxB, idxC);
        float4 x0 = *(const float4*)(xlb + (unsigned)sel_idx(0, idxA, idxB, idxC) + loff);
        float4 x1 = *(const float4*)(xlb + (unsigned)sel_idx(1, idxA, idxB, idxC) + loff);

        const int n2 = n & ~1;
        for (int i = 0; i < n2; i += 2) {
            float4 x2 = *(const float4*)(xlb + (unsigned)s2 + loff);
            float4 x3 = *(const float4*)(xlb + (unsigned)s3 + loff);
            s2 = sel_idx(i + 4, idxA, idxB, idxC);
            s3 = sel_idx(i + 5, idxA, idxB, idxC);

            float l0 = edge_logit(x0, xr, av6, av4);
            float l1 = edge_logit(x1, xr, av6, av4);
            float w0 = exp2f(l0 - lself);
            float w1 = exp2f(l1 - lself);

            den += w0 + w1;
            acc.x = fmaf(w0, x0.x, fmaf(w1, x1.x, acc.x));
            acc.y = fmaf(w0, x0.y, fmaf(w1, x1.y, acc.y));
            acc.z = fmaf(w0, x0.z, fmaf(w1, x1.z, acc.z));
            acc.w = fmaf(w0, x0.w, fmaf(w1, x1.w, acc.w));

            x0 = x2; x1 = x3;
        }
        if (n & 1) {
            // after the loop, x0 holds edge n-1
            float l0 = edge_logit(x0, xr, av6, av4);
            float w0 = exp2f(l0 - lself);
            den += w0;
            acc.x = fmaf(w0, x0.x, acc.x);
            acc.y = fmaf(w0, x0.y, acc.y);
            acc.z = fmaf(w0, x0.z, acc.z);
            acc.w = fmaf(w0, x0.w, acc.w);
        }
    }

    float inv = 1.0f / den;
    float4 bv = *(const float4*)&bias[fbase];
    float4 r;
    r.x = fmaf(acc.x, inv, bv.x);
    r.y = fmaf(acc.y, inv, bv.y);
    r.z = fmaf(acc.z, inv, bv.z);
    r.w = fmaf(acc.w, inv, bv.w);
    *(float4*)((char*)out + ((unsigned)d << 9) + loff) = r;
}

// ---------------- launch (2 kernels) ----------------
extern "C" void kernel_launch(void* const* d_in, const int* in_sizes, int n_in,
                              void* d_out, int out_size) {
    const float* x    = (const float*)d_in[0];
    const int*   ei   = (const int*)d_in[1];
    const float* Wl   = (const float*)d_in[2];
    const float* bl   = (const float*)d_in[3];
    const float* Wr   = (const float*)d_in[4];
    const float* br   = (const float*)d_in[5];
    const float* att  = (const float*)d_in[6];
    const float* bias = (const float*)d_in[7];
    float* out = (float*)d_out;

    const int E = in_sizes[1] / 2;

    gemm_kernel<<<T_NODES / 128, 512>>>(x, Wl, bl, Wr, br, ei, E);
    agg_kernel<<<(T_NODES * 32 + 255) / 256, 256>>>(att, bias, out);
}

// round 16
// speedup vs baseline: 2.0112x; 1.0455x over previous
#include <cuda_runtime.h>
#include <cstdint>

#define T_NODES 80000          // B*N = 16*5000
#define C_DIM   128
#define HF_DIM  128            // H*F = 2*64
#define E_EDGES 1280000
#define SLOT_CAP 96            // do NOT change (R14 regression when 64)
#define LOG2E 1.4426950408889634f

// ---------------- static device scratch (zero-initialized at load) ----------------
__device__ __align__(16) float g_xl[T_NODES * HF_DIM];   // 40.96 MB
__device__ __align__(16) float g_xr[T_NODES * HF_DIM];   // 40.96 MB
__device__ int g_deg[T_NODES];            // invariant: zero at kernel_launch entry
__device__ int g_slot[T_NODES * SLOT_CAP + 8];  // src byte offsets (src<<9); 30.7 MB

// ---------------- tf32 helpers ----------------
__device__ __forceinline__ uint32_t f2tf32(float v) {
    uint32_t r;
    asm("cvt.rna.tf32.f32 %0, %1;" : "=r"(r) : "f"(v));
    return r;
}
__device__ __forceinline__ void mma_tf32(float* d, const uint32_t* a, const uint32_t* b) {
    asm("mma.sync.aligned.m16n8k8.row.col.f32.tf32.tf32.f32 "
        "{%0,%1,%2,%3}, {%4,%5,%6,%7}, {%8,%9}, {%0,%1,%2,%3};"
        : "+f"(d[0]), "+f"(d[1]), "+f"(d[2]), "+f"(d[3])
        : "r"(a[0]), "r"(a[1]), "r"(a[2]), "r"(a[3]),
          "r"(b[0]), "r"(b[1]));
}

// ---------------- K1: fused tf32 GEMM pair + full edge placement (R12 exact) ---
__global__ void __launch_bounds__(512, 1)
gemm_kernel(const float* __restrict__ X,
            const float* __restrict__ Wl, const float* __restrict__ bl,
            const float* __restrict__ Wr, const float* __restrict__ br,
            const int* __restrict__ ei, int E) {
    __shared__ uint32_t A_s[4096];       // [k8(4)][ma(8)][lane(32)][rg(4)] XOR-skewed
    __shared__ uint32_t B_s[2][4096];    // per group: [k8(4)][na(16)][lane(32)][rg(2)]

    const int t = threadIdx.x;

    // edge placement: pos = atomicAdd(deg[dst]); slot[dst*CAP+pos] = src<<9
    {
        const int nthr = gridDim.x * 512;
        int gid = blockIdx.x * 512 + t;
        if ((E & 3) == 0) {
            const int4* __restrict__ s4 = (const int4*)ei;
            const int4* __restrict__ d4 = (const int4*)(ei + E);
            for (int e = gid; e < (E >> 2); e += nthr) {
                int4 s = s4[e];
                int4 dd = d4[e];
                int p0 = atomicAdd(&g_deg[dd.x], 1);
                int p1 = atomicAdd(&g_deg[dd.y], 1);
                int p2 = atomicAdd(&g_deg[dd.z], 1);
                int p3 = atomicAdd(&g_deg[dd.w], 1);
                g_slot[dd.x * SLOT_CAP + p0] = s.x << 9;
                g_slot[dd.y * SLOT_CAP + p1] = s.y << 9;
                g_slot[dd.z * SLOT_CAP + p2] = s.z << 9;
                g_slot[dd.w * SLOT_CAP + p3] = s.w << 9;
            }
        } else {
            for (int e = gid; e < E; e += nthr) {
                int dst = ei[E + e];
                int pos = atomicAdd(&g_deg[dst], 1);
                g_slot[dst * SLOT_CAP + pos] = ei[e] << 9;
            }
        }
    }

    const int lane = t & 31;
    const int wid  = t >> 5;          // 0..15
    const int g    = wid >> 3;        // warp group: 0 = xl, 1 = xr
    const int w8   = wid & 7;
    const int wm   = w8 & 3;
    const int wn   = w8 >> 2;
    const int rowBase = blockIdx.x * 128;

    const int tig = lane & 3;
    const int grp = lane >> 2;

    const float* __restrict__ bvec  = g ? br : bl;
    float* __restrict__ Y           = g ? g_xr : g_xl;

    const int a_row = t >> 2;
    const int a_k8  = t & 3;
    const int a_r   = a_row & 15;
    const int a_ma  = a_row >> 4;
    const int a_atombase = (a_k8 * 8 + a_ma) * 128;
    const int a_skew = a_k8 * 4;

    float d[2][8][4];
#pragma unroll
    for (int ma = 0; ma < 2; ma++)
#pragma unroll
        for (int na = 0; na < 8; na++)
#pragma unroll
            for (int r = 0; r < 4; r++) d[ma][na][r] = 0.f;

#pragma unroll 1
    for (int chunk = 0; chunk < 4; chunk++) {
        const int kc = chunk * 32;

        {
            const float* xp = X + (size_t)(rowBase + a_row) * C_DIM + kc + a_k8 * 8;
            float4 v0 = *(const float4*)xp;
            float4 v1 = *(const float4*)(xp + 4);
            float vv[8] = { v0.x, v0.y, v0.z, v0.w, v1.x, v1.y, v1.z, v1.w };
#pragma unroll
            for (int j = 0; j < 8; j++) {
                int ln = (a_r & 7) * 4 + (j & 3);
                int rg = (a_r >> 3) + 2 * (j >> 2);
                A_s[a_atombase + ((ln * 4 + rg) ^ a_skew)] = f2tf32(vv[j]);
            }
        }
#pragma unroll
        for (int q = 0; q < 8; q++) {
            int combo = q * 16 + wid;
            int bg  = combo >> 6;
            int rem = combo & 63;
            int na  = rem >> 2;
            int k8  = rem & 3;
            const float* __restrict__ WW = bg ? Wr : Wl;
            int k0 = kc + k8 * 8 + tig;
            int n  = na * 8 + grp;
            uint2 val;
            val.x = f2tf32(WW[k0 * HF_DIM + n]);
            val.y = f2tf32(WW[(k0 + 4) * HF_DIM + n]);
            *(uint2*)&B_s[bg][((k8 * 16 + na) * 32 + lane) * 2] = val;
        }
        __syncthreads();

#pragma unroll
        for (int k8 = 0; k8 < 4; k8++) {
            const int skew = k8 * 4;
            uint32_t af[2][4];
#pragma unroll
            for (int ma = 0; ma < 2; ma++) {
                int base = (k8 * 8 + wm * 2 + ma) * 128 + ((lane * 4) ^ skew);
                uint4 h = *(const uint4*)&A_s[base];
                af[ma][0] = h.x; af[ma][1] = h.y; af[ma][2] = h.z; af[ma][3] = h.w;
            }
            uint32_t bf[8][2];
#pragma unroll
            for (int na = 0; na < 8; na++) {
                uint2 b2 = *(const uint2*)&B_s[g][((k8 * 16 + wn * 8 + na) * 32 + lane) * 2];
                bf[na][0] = b2.x; bf[na][1] = b2.y;
            }
#pragma unroll
            for (int ma = 0; ma < 2; ma++)
#pragma unroll
                for (int na = 0; na < 8; na++)
                    mma_tf32(d[ma][na], af[ma], bf[na]);
        }
        __syncthreads();
    }

#pragma unroll
    for (int ma = 0; ma < 2; ma++) {
        int row0 = rowBase + wm * 32 + ma * 16 + grp;
        int row1 = row0 + 8;
#pragma unroll
        for (int na = 0; na < 8; na++) {
            int col = wn * 64 + na * 8 + tig * 2;
            float2 bb = *(const float2*)&bvec[col];
            float2 o0 = { d[ma][na][0] + bb.x, d[ma][na][1] + bb.y };
            float2 o1 = { d[ma][na][2] + bb.x, d[ma][na][3] + bb.y };
            *(float2*)&Y[(size_t)row0 * HF_DIM + col] = o0;
            *(float2*)&Y[(size_t)row1 * HF_DIM + col] = o1;
        }
    }
}

// ---------------- K2: softmax + aggregation (R12 body + n<=27 fast path) -------
__device__ __forceinline__ float edge_logit(float4 xs, float4 xr,
                                            float4 av6, float4 av4) {
    float t0 = xs.x + xr.x, t1 = xs.y + xr.y, t2 = xs.z + xr.z, t3 = xs.w + xr.w;
    float p;
    p = t0 * av6.x;
    p = fmaf(fabsf(t0), av4.x, p);
    p = fmaf(t1, av6.y, p);
    p = fmaf(fabsf(t1), av4.y, p);
    p = fmaf(t2, av6.z, p);
    p = fmaf(fabsf(t2), av4.z, p);
    p = fmaf(t3, av6.w, p);
    p = fmaf(fabsf(t3), av4.w, p);
    p += __shfl_xor_sync(0xffffffffu, p, 1);
    p += __shfl_xor_sync(0xffffffffu, p, 2);
    p += __shfl_xor_sync(0xffffffffu, p, 4);
    p += __shfl_xor_sync(0xffffffffu, p, 8);
    return p;
}

// index for edge i from the warp's register-resident slot row (i uniform)
__device__ __forceinline__ int sel_idx(int i, int a, int b, int c) {
    int r = (i < 32) ? a : ((i < 64) ? b : c);
    return __shfl_sync(0xffffffffu, r, i & 31);
}

__global__ void __launch_bounds__(256, 4)
agg_kernel(const float* __restrict__ att, const float* __restrict__ bias,
           float* __restrict__ out) {
    int warp_id = (blockIdx.x * blockDim.x + threadIdx.x) >> 5;
    int lane = threadIdx.x & 31;
    if (warp_id >= T_NODES) return;
    const int d = warp_id;
    const int fbase = lane * 4;

    const char* __restrict__ xlb = (const char*)g_xl;
    const unsigned loff = (unsigned)lane << 4;   // lane * 16 bytes

    // one coalesced read covers the whole bucket row -> indices live in registers
    const int n = g_deg[d];
    if (lane == 0) g_deg[d] = 0;              // self-clean for next launch
    const int* __restrict__ sp = g_slot + d * SLOT_CAP;
    int idxA = __ldg(&sp[lane]);                       // edges 0..31
    int idxB = (n > 28) ? __ldg(&sp[32 + lane]) : 0;   // edges 32..63
    int idxC = (n > 60) ? __ldg(&sp[64 + lane]) : 0;   // edges 64..95

    float4 a = *(const float4*)&att[fbase];
    float4 av6, av4;
    av6.x = a.x * (0.6f * LOG2E); av4.x = a.x * (0.4f * LOG2E);
    av6.y = a.y * (0.6f * LOG2E); av4.y = a.y * (0.4f * LOG2E);
    av6.z = a.z * (0.6f * LOG2E); av4.z = a.z * (0.4f * LOG2E);
    av6.w = a.w * (0.6f * LOG2E); av4.w = a.w * (0.4f * LOG2E);

    float4 xr  = *(const float4*)((const char*)g_xr + ((unsigned)d << 9) + loff);
    float4 xld = *(const float4*)(xlb + ((unsigned)d << 9) + loff);

    const float lself = edge_logit(xld, xr, av6, av4);   // log2-domain baseline
    float den = 1.0f;
    float4 acc = xld;

    if (n > 0) {
        const int n2 = n & ~1;
        if (n <= 27) {
            // FAST PATH (P ~ 0.997): all indices incl. prefetch overreach (i+5 <= 32... 27+5=32? use <=27 so max shuffle idx = 26+5=31) live in idxA
            int s2 = __shfl_sync(0xffffffffu, idxA, 2);
            int s3 = __shfl_sync(0xffffffffu, idxA, 3);
            float4 x0 = *(const float4*)(xlb + (unsigned)__shfl_sync(0xffffffffu, idxA, 0) + loff);
            float4 x1 = *(const float4*)(xlb + (unsigned)__shfl_sync(0xffffffffu, idxA, 1) + loff);

            for (int i = 0; i < n2; i += 2) {
                float4 x2 = *(const float4*)(xlb + (unsigned)s2 + loff);
                float4 x3 = *(const float4*)(xlb + (unsigned)s3 + loff);
                s2 = __shfl_sync(0xffffffffu, idxA, (i + 4) & 31);
                s3 = __shfl_sync(0xffffffffu, idxA, (i + 5) & 31);

                float l0 = edge_logit(x0, xr, av6, av4);
                float l1 = edge_logit(x1, xr, av6, av4);
                float w0 = exp2f(l0 - lself);
                float w1 = exp2f(l1 - lself);

                den += w0 + w1;
                acc.x = fmaf(w0, x0.x, fmaf(w1, x1.x, acc.x));
                acc.y = fmaf(w0, x0.y, fmaf(w1, x1.y, acc.y));
                acc.z = fmaf(w0, x0.z, fmaf(w1, x1.z, acc.z));
                acc.w = fmaf(w0, x0.w, fmaf(w1, x1.w, acc.w));

                x0 = x2; x1 = x3;
            }
            if (n & 1) {
                float l0 = edge_logit(x0, xr, av6, av4);
                float w0 = exp2f(l0 - lself);
                den += w0;
                acc.x = fmaf(w0, x0.x, acc.x);
                acc.y = fmaf(w0, x0.y, acc.y);
                acc.z = fmaf(w0, x0.z, acc.z);
                acc.w = fmaf(w0, x0.w, acc.w);
            }
        } else {
            // GENERAL PATH (rare): R12 loop with 3-register select
            int s2 = sel_idx(2, idxA, idxB, idxC);
            int s3 = sel_idx(3, idxA, idxB, idxC);
            float4 x0 = *(const float4*)(xlb + (unsigned)sel_idx(0, idxA, idxB, idxC) + loff);
            float4 x1 = *(const float4*)(xlb + (unsigned)sel_idx(1, idxA, idxB, idxC) + loff);

            for (int i = 0; i < n2; i += 2) {
                float4 x2 = *(const float4*)(xlb + (unsigned)s2 + loff);
                float4 x3 = *(const float4*)(xlb + (unsigned)s3 + loff);
                s2 = sel_idx(i + 4, idxA, idxB, idxC);
                s3 = sel_idx(i + 5, idxA, idxB, idxC);

                float l0 = edge_logit(x0, xr, av6, av4);
                float l1 = edge_logit(x1, xr, av6, av4);
                float w0 = exp2f(l0 - lself);
                float w1 = exp2f(l1 - lself);

                den += w0 + w1;
                acc.x = fmaf(w0, x0.x, fmaf(w1, x1.x, acc.x));
                acc.y = fmaf(w0, x0.y, fmaf(w1, x1.y, acc.y));
                acc.z = fmaf(w0, x0.z, fmaf(w1, x1.z, acc.z));
                acc.w = fmaf(w0, x0.w, fmaf(w1, x1.w, acc.w));

                x0 = x2; x1 = x3;
            }
            if (n & 1) {
                float l0 = edge_logit(x0, xr, av6, av4);
                float w0 = exp2f(l0 - lself);
                den += w0;
                acc.x = fmaf(w0, x0.x, acc.x);
                acc.y = fmaf(w0, x0.y, acc.y);
                acc.z = fmaf(w0, x0.z, acc.z);
                acc.w = fmaf(w0, x0.w, acc.w);
            }
        }
    }

    float inv = 1.0f / den;
    float4 bv = *(const float4*)&bias[fbase];
    float4 r;
    r.x = fmaf(acc.x, inv, bv.x);
    r.y = fmaf(acc.y, inv, bv.y);
    r.z = fmaf(acc.z, inv, bv.z);
    r.w = fmaf(acc.w, inv, bv.w);
    *(float4*)((char*)out + ((unsigned)d << 9) + loff) = r;
}

// ---------------- launch (2 kernels) ----------------
extern "C" void kernel_launch(void* const* d_in, const int* in_sizes, int n_in,
                              void* d_out, int out_size) {
    const float* x    = (const float*)d_in[0];
    const int*   ei   = (const int*)d_in[1];
    const float* Wl   = (const float*)d_in[2];
    const float* bl   = (const float*)d_in[3];
    const float* Wr   = (const float*)d_in[4];
    const float* br   = (const float*)d_in[5];
    const float* att  = (const float*)d_in[6];
    const float* bias = (const float*)d_in[7];
    float* out = (float*)d_out;

    const int E = in_sizes[1] / 2;

    gemm_kernel<<<T_NODES / 128, 512>>>(x, Wl, bl, Wr, br, ei, E);
    agg_kernel<<<(T_NODES * 32 + 255) / 256, 256>>>(att, bias, out);
}